// round 16
// baseline (speedup 1.0000x reference)
#include <cuda_runtime.h>
#include <math.h>

#define BB 64
#define SS 128
#define FF 16
#define HH 64
#define G4H 256
#define QN 192

// ---------------- scratch (static device globals; no allocation) -------------
__device__ float g_lstm[2][FF][BB][SS][HH];      // 67 MB
__device__ float g_pbar[2 * FF * BB * 2 * SS];   // 2 MB: colmean probs per head

// ---------------- helpers ----------------------------------------------------
__device__ __forceinline__ float sigm_f(float x) {
    return __fdividef(1.f, 1.f + __expf(-x));
}
__device__ __forceinline__ float tanh_f(float x) {
    x = fminf(fmaxf(x, -10.f), 10.f);
    float e = __expf(2.f * x);
    return __fdividef(e - 1.f, e + 1.f);
}

// ---------------- LSTM kernel (R15-passing form, untouched) -------------------
#define LCH 8

__global__ void __launch_bounds__(256, 2) lstm_kernel(
    const float* __restrict__ x0, const float* __restrict__ x1,
    const float* __restrict__ Wih0, const float* __restrict__ Whh0,
    const float* __restrict__ bih0, const float* __restrict__ bhh0,
    const float* __restrict__ Wih1, const float* __restrict__ Whh1,
    const float* __restrict__ bih1, const float* __restrict__ bhh1)
{
    __shared__ float h_sh[LCH * 64];
    __shared__ float c_sh[LCH * 64];
    __shared__ float g_sh[LCH * 256];
    __shared__ float xs[LCH];

    const int t  = threadIdx.x;                 // gate index
    const int f  = blockIdx.y;
    const int b0 = blockIdx.x * LCH;
    const int br = blockIdx.z;

    const float* x   = br ? x1   : x0;
    const float* Wih = br ? Wih1 : Wih0;
    const float* Whh = br ? Whh1 : Whh0;
    const float* bih = br ? bih1 : bih0;
    const float* bhh = br ? bhh1 : bhh0;

    // register-resident Whh row for gate t (64 floats)
    float4 w[16];
    const float4* wrow = (const float4*)(Whh + (f * G4H + t) * HH);
    #pragma unroll
    for (int c = 0; c < 16; c++) w[c] = wrow[c];

    const float wih_r  = Wih[f * G4H + t];
    const float bias_r = bih[f * G4H + t] + bhh[f * G4H + t];

    for (int i = t; i < LCH * 64; i += 256) { h_sh[i] = 0.f; c_sh[i] = 0.f; }
    if (t < LCH) xs[t] = x[((b0 + t) * SS + 0) * FF + f];
    __syncthreads();

    float* outbase = &g_lstm[br][f][b0][0][0];   // [LCH][S][H] slab

    float xnext = 0.f;
    for (int s = 0; s < SS; s++) {
        if (t < LCH && s + 1 < SS) xnext = x[((b0 + t) * SS + s + 1) * FF + f];

        float acc[LCH];
        #pragma unroll
        for (int b = 0; b < LCH; b++) acc[b] = fmaf(xs[b], wih_r, bias_r);

        const float4* h4 = (const float4*)h_sh;
        #pragma unroll
        for (int hc = 0; hc < 16; hc++) {
            float4 wv = w[hc];
            #pragma unroll
            for (int b = 0; b < LCH; b++) {
                float4 hv = h4[b * 16 + hc];     // broadcast
                acc[b] = fmaf(wv.x, hv.x, acc[b]);
                acc[b] = fmaf(wv.y, hv.y, acc[b]);
                acc[b] = fmaf(wv.z, hv.z, acc[b]);
                acc[b] = fmaf(wv.w, hv.w, acc[b]);
            }
        }
        #pragma unroll
        for (int b = 0; b < LCH; b++) g_sh[b * 256 + t] = acc[b];
        __syncthreads();

        #pragma unroll
        for (int ci = 0; ci < 2; ci++) {
            int idx = t + ci * 256;
            int bb = idx >> 6;
            int jj = idx & 63;
            float gi = g_sh[bb * 256 + jj];
            float gf = g_sh[bb * 256 + 64 + jj];
            float gg = g_sh[bb * 256 + 128 + jj];
            float go = g_sh[bb * 256 + 192 + jj];
            float cc = sigm_f(gf) * c_sh[bb * 64 + jj] + sigm_f(gi) * tanh_f(gg);
            float hh = sigm_f(go) * tanh_f(cc);
            c_sh[bb * 64 + jj] = cc;
            h_sh[bb * 64 + jj] = hh;
            outbase[(bb * SS + s) * HH + jj] = hh;
        }
        if (t < LCH) xs[t] = xnext;
        __syncthreads();
    }
}

// ---------------- fused QK + attention core ----------------------------------
#define XPAD 68
#define ATTN_SMEM ((2*128*XPAD + 32*128) * 4)

__global__ void __launch_bounds__(512, 1) attn_kernel(
    const float* __restrict__ Wq0, const float* __restrict__ bq0,
    const float* __restrict__ Wq1, const float* __restrict__ bq1,
    float* __restrict__ d_out)
{
    extern __shared__ float sm[];
    float* Xs   = sm;                      // [128][68]   (phase 1)
    float* Wsh  = sm + 128 * XPAD;         // [128][68]   (phase 1)
    float* Qs   = sm;                      // [128][68]   (phase 2, aliases Xs)
    float* Ks   = sm + 128 * XPAD;         // [128][68]   (phase 2, aliases Wsh)
    float* psum = sm + 2 * 128 * XPAD;     // [32][128]

    const int tid = threadIdx.x;
    const int tx = tid & 15, ty = tid >> 4;   // ty: 0..31
    const int b = blockIdx.x, f = blockIdx.y, br = blockIdx.z;

    const float* Wq = br ? Wq1 : Wq0;
    const float* bq = br ? bq1 : bq0;

    const float* Xg = &g_lstm[br][f][b][0][0];     // [128][64] in gmem

    const float4* X4 = (const float4*)Xg;
    #pragma unroll
    for (int l = 0; l < 4; l++) {
        int li = tid + l * 512;              // 0..2047
        int s = li >> 4, c4 = li & 15;
        *(float4*)&Xs[s * XPAD + c4 * 4] = X4[li];
    }
    const float4* W4 = (const float4*)(Wq + (size_t)f * QN * HH);
    #pragma unroll
    for (int l = 0; l < 4; l++) {
        int li = tid + l * 512;              // rows 0..127 (Q,K)
        int g = li >> 4, c4 = li & 15;
        *(float4*)&Wsh[g * XPAD + c4 * 4] = W4[li];
    }
    __syncthreads();

    float acc[4][8];
    {
        #pragma unroll
        for (int j = 0; j < 8; j++) {
            float bj = bq[f * QN + tx + 16 * j];
            #pragma unroll
            for (int i = 0; i < 4; i++) acc[i][j] = bj;
        }
        #pragma unroll
        for (int k4 = 0; k4 < 16; k4++) {
            float4 wv[8];
            #pragma unroll
            for (int j = 0; j < 8; j++)
                wv[j] = *(const float4*)&Wsh[(tx + 16 * j) * XPAD + k4 * 4];
            #pragma unroll
            for (int i = 0; i < 4; i++) {
                float4 xv = *(const float4*)&Xs[(ty * 4 + i) * XPAD + k4 * 4];
                #pragma unroll
                for (int j = 0; j < 8; j++) {
                    acc[i][j] = fmaf(xv.x, wv[j].x, acc[i][j]);
                    acc[i][j] = fmaf(xv.y, wv[j].y, acc[i][j]);
                    acc[i][j] = fmaf(xv.z, wv[j].z, acc[i][j]);
                    acc[i][j] = fmaf(xv.w, wv[j].w, acc[i][j]);
                }
            }
        }
    }
    __syncthreads();   // ALL reads of Xs/Wsh complete before aliased writes
    #pragma unroll
    for (int i = 0; i < 4; i++) {
        int s = ty * 4 + i;
        #pragma unroll
        for (int j = 0; j < 4; j++) Qs[s * XPAD + tx + 16 * j] = acc[i][j];
        #pragma unroll
        for (int j = 4; j < 8; j++) Ks[s * XPAD + tx + 16 * (j - 4)] = acc[i][j];
    }
    __syncthreads();

    float* attn_base = d_out + 128 + (size_t)br * FF * BB * SS * SS
                     + ((size_t)(f * BB + b)) * SS * SS;
    const float scale = 0.17677669529663687f;  // 1/sqrt(32)

    float p0[4][8];                    // head-0 probs in regs

    for (int n = 0; n < 2; n++) {
        const int off = n * 32;
        float c[4][8];
        #pragma unroll
        for (int i = 0; i < 4; i++)
            #pragma unroll
            for (int j = 0; j < 8; j++) c[i][j] = 0.f;

        #pragma unroll
        for (int d4 = 0; d4 < 8; d4++) {
            float4 kv[8];
            #pragma unroll
            for (int j = 0; j < 8; j++)
                kv[j] = *(const float4*)&Ks[(tx + 16 * j) * XPAD + off + d4 * 4];
            #pragma unroll
            for (int i = 0; i < 4; i++) {
                float4 qv = *(const float4*)&Qs[(ty * 4 + i) * XPAD + off + d4 * 4];
                #pragma unroll
                for (int j = 0; j < 8; j++) {
                    c[i][j] = fmaf(qv.x, kv[j].x, c[i][j]);
                    c[i][j] = fmaf(qv.y, kv[j].y, c[i][j]);
                    c[i][j] = fmaf(qv.z, kv[j].z, c[i][j]);
                    c[i][j] = fmaf(qv.w, kv[j].w, c[i][j]);
                }
            }
        }

        #pragma unroll
        for (int i = 0; i < 4; i++) {
            float m = c[i][0] * scale;
            #pragma unroll
            for (int j = 0; j < 8; j++) { c[i][j] *= scale; m = fmaxf(m, c[i][j]); }
            #pragma unroll
            for (int o = 8; o >= 1; o >>= 1)
                m = fmaxf(m, __shfl_xor_sync(0xffffffffu, m, o, 16));
            float s2 = 0.f;
            #pragma unroll
            for (int j = 0; j < 8; j++) { c[i][j] = __expf(c[i][j] - m); s2 += c[i][j]; }
            #pragma unroll
            for (int o = 8; o >= 1; o >>= 1)
                s2 += __shfl_xor_sync(0xffffffffu, s2, o, 16);
            float inv = __fdividef(1.f, s2);
            #pragma unroll
            for (int j = 0; j < 8; j++) c[i][j] *= inv;
        }

        float colsum[8];
        #pragma unroll
        for (int j = 0; j < 8; j++) colsum[j] = 0.f;
        #pragma unroll
        for (int i = 0; i < 4; i++) {
            float* ab = attn_base + (ty * 4 + i) * SS;
            #pragma unroll
            for (int j = 0; j < 8; j++) {
                float p = c[i][j];
                colsum[j] += p;
                if (n == 0) p0[i][j] = p;
                else        ab[tx + 16 * j] = 0.5f * (p0[i][j] + p);
            }
        }
        #pragma unroll
        for (int j = 0; j < 8; j++) psum[ty * 128 + tx + 16 * j] = colsum[j];
        __syncthreads();

        // two-stage colmean: 512 threads x 8 rows, then 128 x 4
        {
            int g2 = tid >> 7, col = tid & 127;
            float s2 = 0.f;
            #pragma unroll
            for (int yy = 0; yy < 8; yy++) s2 += psum[(g2 * 8 + yy) * 128 + col];
            psum[(g2 * 8) * 128 + col] = s2;   // own-row overwrite after own reads
        }
        __syncthreads();
        if (tid < 128) {
            float s2 = psum[tid] + psum[8 * 128 + tid]
                     + psum[16 * 128 + tid] + psum[24 * 128 + tid];
            g_pbar[((((size_t)br * FF + f) * BB + b) * 2 + n) * SS + tid]
                = s2 * (1.f / 128.f);
        }
        __syncthreads();   // psum reused by next head
    }
}

// ---------------- tail: pooled (per warp-slab) + static/time MLPs + fc --------
// grid 64 (one block per batch), 512 threads = 16 warps; warp w owns slabs
// 2w, 2w+1 (slab = br*16+f). Warp-local phases (no block barriers until fc).
__global__ void __launch_bounds__(512) tail_kernel(
    const float* __restrict__ Wq0, const float* __restrict__ bq0,
    const float* __restrict__ Wo0, const float* __restrict__ bo0,
    const float* __restrict__ Wq1, const float* __restrict__ bq1,
    const float* __restrict__ Wo1, const float* __restrict__ bo1,
    const float* __restrict__ stat, const float* __restrict__ tg,
    const float* __restrict__ d1w, const float* __restrict__ d1b,
    const float* __restrict__ d2w, const float* __restrict__ d2b,
    const float* __restrict__ t1w, const float* __restrict__ t1b,
    const float* __restrict__ t2w, const float* __restrict__ t2b,
    const float* __restrict__ fcw, const float* __restrict__ fcb,
    float* __restrict__ out)
{
    __shared__ float scratch[16][256];   // per-warp: pbar copy -> ys -> obar
    __shared__ float comb[2048];
    __shared__ float s1[64], t1s[16], tail2[40];
    __shared__ float red[2][512];

    const int tid  = threadIdx.x;
    const int wid  = tid >> 5;
    const int lane = tid & 31;
    const int b    = blockIdx.x;

    #pragma unroll
    for (int sl = 0; sl < 2; sl++) {
        const int slab = wid * 2 + sl;
        const int br = slab >> 4, f = slab & 15;
        const float* Wq   = br ? Wq1 : Wq0;
        const float* bq   = br ? bq1 : bq0;
        const float* Wout = br ? Wo1 : Wo0;
        const float* bout = br ? bo1 : bo0;

        const float* Xg = &g_lstm[br][f][b][0][0];               // [128][64]
        const float* pb = &g_pbar[(((size_t)br * FF + f) * BB + b) * 2 * SS];

        // stage pbar (2 heads x 128) into warp scratch
        #pragma unroll
        for (int i = 0; i < 8; i++) scratch[wid][lane + i * 32] = pb[lane + i * 32];
        __syncwarp();

        // ys[h][d] = sum_k pbar[h][k] * X[k][d]; lane owns d = lane, lane+32
        float y00 = 0.f, y01 = 0.f, y10 = 0.f, y11 = 0.f;
        #pragma unroll 4
        for (int k = 0; k < 128; k++) {
            float xlo = Xg[k * HH + lane];
            float xhi = Xg[k * HH + lane + 32];
            float pa = scratch[wid][k];
            float pc = scratch[wid][128 + k];
            y00 = fmaf(pa, xlo, y00);
            y01 = fmaf(pa, xhi, y01);
            y10 = fmaf(pc, xlo, y10);
            y11 = fmaf(pc, xhi, y11);
        }
        __syncwarp();
        scratch[wid][lane]      = y00;   // ys[0][lane]
        scratch[wid][32 + lane] = y01;   // ys[0][lane+32]
        scratch[wid][64 + lane] = y10;   // ys[1][lane]
        scratch[wid][96 + lane] = y11;   // ys[1][lane+32]
        __syncwarp();

        // obar[c] = bv[c] + ys[c>>5] . Wv_row(128+c); lane owns c = lane, lane+32
        float o1 = bq[f * QN + 128 + lane];
        float o2 = bq[f * QN + 160 + lane];
        {
            const float4* wr1 = (const float4*)(Wq + ((size_t)f * QN + 128 + lane) * HH);
            const float4* wr2 = (const float4*)(Wq + ((size_t)f * QN + 160 + lane) * HH);
            #pragma unroll
            for (int d4 = 0; d4 < 16; d4++) {
                float4 w1 = wr1[d4], w2 = wr2[d4];
                o1 = fmaf(scratch[wid][d4 * 4 + 0], w1.x, o1);       // h=0
                o1 = fmaf(scratch[wid][d4 * 4 + 1], w1.y, o1);
                o1 = fmaf(scratch[wid][d4 * 4 + 2], w1.z, o1);
                o1 = fmaf(scratch[wid][d4 * 4 + 3], w1.w, o1);
                o2 = fmaf(scratch[wid][64 + d4 * 4 + 0], w2.x, o2);  // h=1
                o2 = fmaf(scratch[wid][64 + d4 * 4 + 1], w2.y, o2);
                o2 = fmaf(scratch[wid][64 + d4 * 4 + 2], w2.z, o2);
                o2 = fmaf(scratch[wid][64 + d4 * 4 + 3], w2.w, o2);
            }
        }
        __syncwarp();
        scratch[wid][128 + lane] = o1;   // obar[lane]
        scratch[wid][160 + lane] = o2;   // obar[lane+32]
        __syncwarp();

        // pooled[o] = bout[o] + obar . Wout_row(o); lane owns o = lane, lane+32
        float p1 = bout[f * 64 + lane];
        float p2 = bout[f * 64 + 32 + lane];
        {
            const float4* wr1 = (const float4*)(Wout + (size_t)f * 4096 + lane * 64);
            const float4* wr2 = (const float4*)(Wout + (size_t)f * 4096 + (32 + lane) * 64);
            #pragma unroll
            for (int h4 = 0; h4 < 16; h4++) {
                float4 w1 = wr1[h4], w2 = wr2[h4];
                float a0 = scratch[wid][128 + h4 * 4 + 0];
                float a1 = scratch[wid][128 + h4 * 4 + 1];
                float a2 = scratch[wid][128 + h4 * 4 + 2];
                float a3 = scratch[wid][128 + h4 * 4 + 3];
                p1 = fmaf(a0, w1.x, p1); p1 = fmaf(a1, w1.y, p1);
                p1 = fmaf(a2, w1.z, p1); p1 = fmaf(a3, w1.w, p1);
                p2 = fmaf(a0, w2.x, p2); p2 = fmaf(a1, w2.y, p2);
                p2 = fmaf(a2, w2.z, p2); p2 = fmaf(a3, w2.w, p2);
            }
        }
        comb[br * 1024 + f * 64 + lane]      = p1;
        comb[br * 1024 + f * 64 + 32 + lane] = p2;
        __syncwarp();
    }

    // ---- static/time MLPs ----
    __syncthreads();
    if (tid < 64) {
        float a = d1b[tid];
        #pragma unroll
        for (int i = 0; i < 32; i++) a = fmaf(stat[b * 32 + i], d1w[tid * 32 + i], a);
        s1[tid] = fmaxf(a, 0.f);
    }
    if (tid >= 64 && tid < 80) {
        int j = tid - 64;
        t1s[j] = fmaxf(fmaf(tg[b], t1w[j], t1b[j]), 0.f);
    }
    __syncthreads();
    if (tid < 32) {
        float a = d2b[tid];
        #pragma unroll
        for (int i = 0; i < 64; i++) a = fmaf(s1[i], d2w[tid * 64 + i], a);
        tail2[tid] = fmaxf(a, 0.f);
    }
    if (tid >= 32 && tid < 40) {
        int j = tid - 32;
        float a = t2b[j];
        #pragma unroll
        for (int i = 0; i < 16; i++) a = fmaf(t1s[i], t2w[j * 16 + i], a);
        tail2[tid] = fmaxf(a, 0.f);
    }
    __syncthreads();

    // ---- fc: 512-wide partial dot + tree reduce ----
    float a0 = 0.f, a1 = 0.f;
    for (int c = tid; c < 2088; c += 512) {
        float v = (c < 2048) ? comb[c] : tail2[c - 2048];
        a0 = fmaf(v, fcw[c], a0);
        a1 = fmaf(v, fcw[2088 + c], a1);
    }
    red[0][tid] = a0; red[1][tid] = a1;
    __syncthreads();
    for (int off = 256; off >= 1; off >>= 1) {
        if (tid < off) {
            red[0][tid] += red[0][tid + off];
            red[1][tid] += red[1][tid + off];
        }
        __syncthreads();
    }
    if (tid == 0) {
        out[b * 2 + 0] = red[0][0] + fcb[0];
        out[b * 2 + 1] = red[1][0] + fcb[1];
    }
}

// ---------------- launch ------------------------------------------------------
extern "C" void kernel_launch(void* const* d_in, const int* in_sizes, int n_in,
                              void* d_out, int out_size)
{
    (void)in_sizes; (void)n_in; (void)out_size;
    float* out = (float*)d_out;

    cudaFuncSetAttribute(attn_kernel, cudaFuncAttributeMaxDynamicSharedMemorySize, ATTN_SMEM);

    lstm_kernel<<<dim3(8, 16, 2), 256>>>(
        (const float*)d_in[0], (const float*)d_in[1],
        (const float*)d_in[4], (const float*)d_in[5],
        (const float*)d_in[6], (const float*)d_in[7],
        (const float*)d_in[8], (const float*)d_in[9],
        (const float*)d_in[10], (const float*)d_in[11]);

    attn_kernel<<<dim3(64, 16, 2), 512, ATTN_SMEM>>>(
        (const float*)d_in[12], (const float*)d_in[13],
        (const float*)d_in[16], (const float*)d_in[17],
        out);

    tail_kernel<<<64, 512>>>(
        (const float*)d_in[12], (const float*)d_in[13],
        (const float*)d_in[14], (const float*)d_in[15],
        (const float*)d_in[16], (const float*)d_in[17],
        (const float*)d_in[18], (const float*)d_in[19],
        (const float*)d_in[2], (const float*)d_in[3],
        (const float*)d_in[20], (const float*)d_in[21],
        (const float*)d_in[22], (const float*)d_in[23],
        (const float*)d_in[24], (const float*)d_in[25],
        (const float*)d_in[26], (const float*)d_in[27],
        (const float*)d_in[28], (const float*)d_in[29],
        out);
}

// round 17
// speedup vs baseline: 1.0586x; 1.0586x over previous
#include <cuda_runtime.h>
#include <math.h>

#define BB 64
#define SS 128
#define FF 16
#define HH 64
#define G4H 256
#define QN 192

// ---------------- scratch (static device globals; no allocation) -------------
__device__ float g_lstm[2][FF][BB][SS][HH];      // 67 MB
__device__ float g_pbar[2 * FF * BB * 2 * SS];   // 2 MB: colmean probs per head
__device__ float g_comb[BB][2 * FF * HH];        // 512 KB

// ---------------- helpers ----------------------------------------------------
__device__ __forceinline__ float sigm_f(float x) {
    return __fdividef(1.f, 1.f + __expf(-x));
}
__device__ __forceinline__ float tanh_f(float x) {
    x = fminf(fmaxf(x, -10.f), 10.f);
    float e = __expf(2.f * x);
    return __fdividef(e - 1.f, e + 1.f);
}

// ---------------- LSTM kernel (R15-passing form, untouched) -------------------
#define LCH 8

__global__ void __launch_bounds__(256, 2) lstm_kernel(
    const float* __restrict__ x0, const float* __restrict__ x1,
    const float* __restrict__ Wih0, const float* __restrict__ Whh0,
    const float* __restrict__ bih0, const float* __restrict__ bhh0,
    const float* __restrict__ Wih1, const float* __restrict__ Whh1,
    const float* __restrict__ bih1, const float* __restrict__ bhh1)
{
    __shared__ float h_sh[LCH * 64];
    __shared__ float c_sh[LCH * 64];
    __shared__ float g_sh[LCH * 256];
    __shared__ float xs[LCH];

    const int t  = threadIdx.x;                 // gate index
    const int f  = blockIdx.y;
    const int b0 = blockIdx.x * LCH;
    const int br = blockIdx.z;

    const float* x   = br ? x1   : x0;
    const float* Wih = br ? Wih1 : Wih0;
    const float* Whh = br ? Whh1 : Whh0;
    const float* bih = br ? bih1 : bih0;
    const float* bhh = br ? bhh1 : bhh0;

    // register-resident Whh row for gate t (64 floats)
    float4 w[16];
    const float4* wrow = (const float4*)(Whh + (f * G4H + t) * HH);
    #pragma unroll
    for (int c = 0; c < 16; c++) w[c] = wrow[c];

    const float wih_r  = Wih[f * G4H + t];
    const float bias_r = bih[f * G4H + t] + bhh[f * G4H + t];

    for (int i = t; i < LCH * 64; i += 256) { h_sh[i] = 0.f; c_sh[i] = 0.f; }
    if (t < LCH) xs[t] = x[((b0 + t) * SS + 0) * FF + f];
    __syncthreads();

    float* outbase = &g_lstm[br][f][b0][0][0];   // [LCH][S][H] slab

    float xnext = 0.f;
    for (int s = 0; s < SS; s++) {
        // prefetch next step's x (latency hidden under the gates GEMM)
        if (t < LCH && s + 1 < SS) xnext = x[((b0 + t) * SS + s + 1) * FF + f];

        float acc[LCH];
        #pragma unroll
        for (int b = 0; b < LCH; b++) acc[b] = fmaf(xs[b], wih_r, bias_r);

        const float4* h4 = (const float4*)h_sh;
        #pragma unroll
        for (int hc = 0; hc < 16; hc++) {
            float4 wv = w[hc];
            #pragma unroll
            for (int b = 0; b < LCH; b++) {
                float4 hv = h4[b * 16 + hc];     // broadcast
                acc[b] = fmaf(wv.x, hv.x, acc[b]);
                acc[b] = fmaf(wv.y, hv.y, acc[b]);
                acc[b] = fmaf(wv.z, hv.z, acc[b]);
                acc[b] = fmaf(wv.w, hv.w, acc[b]);
            }
        }
        #pragma unroll
        for (int b = 0; b < LCH; b++) g_sh[b * 256 + t] = acc[b];
        __syncthreads();

        // epilogue: 512 cells, 2 per thread
        #pragma unroll
        for (int ci = 0; ci < 2; ci++) {
            int idx = t + ci * 256;
            int bb = idx >> 6;
            int jj = idx & 63;
            float gi = g_sh[bb * 256 + jj];
            float gf = g_sh[bb * 256 + 64 + jj];
            float gg = g_sh[bb * 256 + 128 + jj];
            float go = g_sh[bb * 256 + 192 + jj];
            float cc = sigm_f(gf) * c_sh[bb * 64 + jj] + sigm_f(gi) * tanh_f(gg);
            float hh = sigm_f(go) * tanh_f(cc);
            c_sh[bb * 64 + jj] = cc;
            h_sh[bb * 64 + jj] = hh;
            outbase[(bb * SS + s) * HH + jj] = hh;
        }
        if (t < LCH) xs[t] = xnext;
        __syncthreads();
    }
}

// ---------------- fused QK + attention core (tail stripped) -------------------
// block per (b, f, branch), 512 threads, 1 CTA/SM. Computes Q,K in-block,
// scores, softmax, head-mean probs to d_out, colmean(probs) to g_pbar.
#define XPAD 68
#define ATTN_SMEM ((2*128*XPAD + 32*128) * 4)

__global__ void __launch_bounds__(512, 1) attn_kernel(
    const float* __restrict__ Wq0, const float* __restrict__ bq0,
    const float* __restrict__ Wq1, const float* __restrict__ bq1,
    float* __restrict__ d_out)
{
    extern __shared__ float sm[];
    float* Xs   = sm;                      // [128][68]   (phase 1)
    float* Wsh  = sm + 128 * XPAD;         // [128][68]   (phase 1)
    float* Qs   = sm;                      // [128][68]   (phase 2, aliases Xs)
    float* Ks   = sm + 128 * XPAD;         // [128][68]   (phase 2, aliases Wsh)
    float* psum = sm + 2 * 128 * XPAD;     // [32][128]

    const int tid = threadIdx.x;
    const int tx = tid & 15, ty = tid >> 4;   // ty: 0..31
    const int b = blockIdx.x, f = blockIdx.y, br = blockIdx.z;

    const float* Wq = br ? Wq1 : Wq0;
    const float* bq = br ? bq1 : bq0;

    const float* Xg = &g_lstm[br][f][b][0][0];     // [128][64] in gmem

    // ---- stage X [128][64] and Wqk [128][64] ----
    const float4* X4 = (const float4*)Xg;
    #pragma unroll
    for (int l = 0; l < 4; l++) {
        int li = tid + l * 512;              // 0..2047
        int s = li >> 4, c4 = li & 15;
        *(float4*)&Xs[s * XPAD + c4 * 4] = X4[li];
    }
    const float4* W4 = (const float4*)(Wq + (size_t)f * QN * HH);
    #pragma unroll
    for (int l = 0; l < 4; l++) {
        int li = tid + l * 512;              // rows 0..127 (Q,K)
        int g = li >> 4, c4 = li & 15;
        *(float4*)&Wsh[g * XPAD + c4 * 4] = W4[li];
    }
    __syncthreads();

    // ---- QK GEMM: [128 rows][128 gate-cols], acc held across the barrier ----
    float acc[4][8];
    {
        #pragma unroll
        for (int j = 0; j < 8; j++) {
            float bj = bq[f * QN + tx + 16 * j];
            #pragma unroll
            for (int i = 0; i < 4; i++) acc[i][j] = bj;
        }
        #pragma unroll
        for (int k4 = 0; k4 < 16; k4++) {
            float4 wv[8];
            #pragma unroll
            for (int j = 0; j < 8; j++)
                wv[j] = *(const float4*)&Wsh[(tx + 16 * j) * XPAD + k4 * 4];
            #pragma unroll
            for (int i = 0; i < 4; i++) {
                float4 xv = *(const float4*)&Xs[(ty * 4 + i) * XPAD + k4 * 4];
                #pragma unroll
                for (int j = 0; j < 8; j++) {
                    acc[i][j] = fmaf(xv.x, wv[j].x, acc[i][j]);
                    acc[i][j] = fmaf(xv.y, wv[j].y, acc[i][j]);
                    acc[i][j] = fmaf(xv.z, wv[j].z, acc[i][j]);
                    acc[i][j] = fmaf(xv.w, wv[j].w, acc[i][j]);
                }
            }
        }
    }
    __syncthreads();   // ALL reads of Xs/Wsh complete before aliased writes
    #pragma unroll
    for (int i = 0; i < 4; i++) {
        int s = ty * 4 + i;
        #pragma unroll
        for (int j = 0; j < 4; j++) Qs[s * XPAD + tx + 16 * j] = acc[i][j];
        #pragma unroll
        for (int j = 4; j < 8; j++) Ks[s * XPAD + tx + 16 * (j - 4)] = acc[i][j];
    }
    __syncthreads();

    float* attn_base = d_out + 128 + (size_t)br * FF * BB * SS * SS
                     + ((size_t)(f * BB + b)) * SS * SS;
    const float scale = 0.17677669529663687f;  // 1/sqrt(32)

    float p0[4][8];                    // head-0 probs in regs

    for (int n = 0; n < 2; n++) {
        const int off = n * 32;
        float c[4][8];
        #pragma unroll
        for (int i = 0; i < 4; i++)
            #pragma unroll
            for (int j = 0; j < 8; j++) c[i][j] = 0.f;

        // vectorized over d: 8 float4 chunks of the 32-dim head
        #pragma unroll
        for (int d4 = 0; d4 < 8; d4++) {
            float4 kv[8];
            #pragma unroll
            for (int j = 0; j < 8; j++)
                kv[j] = *(const float4*)&Ks[(tx + 16 * j) * XPAD + off + d4 * 4];
            #pragma unroll
            for (int i = 0; i < 4; i++) {
                float4 qv = *(const float4*)&Qs[(ty * 4 + i) * XPAD + off + d4 * 4];
                #pragma unroll
                for (int j = 0; j < 8; j++) {
                    c[i][j] = fmaf(qv.x, kv[j].x, c[i][j]);
                    c[i][j] = fmaf(qv.y, kv[j].y, c[i][j]);
                    c[i][j] = fmaf(qv.z, kv[j].z, c[i][j]);
                    c[i][j] = fmaf(qv.w, kv[j].w, c[i][j]);
                }
            }
        }

        // scale + row softmax (row = 16 lanes of one half-warp)
        #pragma unroll
        for (int i = 0; i < 4; i++) {
            float m = c[i][0] * scale;
            #pragma unroll
            for (int j = 0; j < 8; j++) { c[i][j] *= scale; m = fmaxf(m, c[i][j]); }
            #pragma unroll
            for (int o = 8; o >= 1; o >>= 1)
                m = fmaxf(m, __shfl_xor_sync(0xffffffffu, m, o, 16));
            float s2 = 0.f;
            #pragma unroll
            for (int j = 0; j < 8; j++) { c[i][j] = __expf(c[i][j] - m); s2 += c[i][j]; }
            #pragma unroll
            for (int o = 8; o >= 1; o >>= 1)
                s2 += __shfl_xor_sync(0xffffffffu, s2, o, 16);
            float inv = __fdividef(1.f, s2);
            #pragma unroll
            for (int j = 0; j < 8; j++) c[i][j] *= inv;
        }

        // head-mean probs: head0 in regs, single store at head1
        float colsum[8];
        #pragma unroll
        for (int j = 0; j < 8; j++) colsum[j] = 0.f;
        #pragma unroll
        for (int i = 0; i < 4; i++) {
            float* ab = attn_base + (ty * 4 + i) * SS;
            #pragma unroll
            for (int j = 0; j < 8; j++) {
                float p = c[i][j];
                colsum[j] += p;
                if (n == 0) p0[i][j] = p;
                else        ab[tx + 16 * j] = 0.5f * (p0[i][j] + p);
            }
        }
        #pragma unroll
        for (int j = 0; j < 8; j++) psum[ty * 128 + tx + 16 * j] = colsum[j];
        __syncthreads();

        // colmean to gmem (post_kernel consumes)
        if (tid < 128) {
            float s2 = 0.f;
            #pragma unroll
            for (int yy = 0; yy < 32; yy++) s2 += psum[yy * 128 + tid];
            g_pbar[((((size_t)br * FF + f) * BB + b) * 2 + n) * SS + tid]
                = s2 * (1.f / 128.f);
        }
        __syncthreads();   // psum reused by next head
    }
}

// ---------------- post: pooled = ((pbar @ X) @ Wv^T + bv) @ Wout^T + bout -----
// grid (64, 16, 2), 128 threads. All phases full-ish width, coalesced X reads.
__global__ void __launch_bounds__(128) post_kernel(
    const float* __restrict__ Wq0, const float* __restrict__ bq0,
    const float* __restrict__ Wo0, const float* __restrict__ bo0,
    const float* __restrict__ Wq1, const float* __restrict__ bq1,
    const float* __restrict__ Wo1, const float* __restrict__ bo1)
{
    __shared__ float ys[2][64];
    __shared__ float obar[64];

    const int tid = threadIdx.x;
    const int b = blockIdx.x, f = blockIdx.y, br = blockIdx.z;

    const float* Wq   = br ? Wq1 : Wq0;
    const float* bq   = br ? bq1 : bq0;
    const float* Wout = br ? Wo1 : Wo0;
    const float* bout = br ? bo1 : bo0;

    const float* Xg = &g_lstm[br][f][b][0][0];     // [128][64]
    const float* pb = &g_pbar[(((size_t)br * FF + f) * BB + b) * 2 * SS];

    // ys[h][d] = sum_k pbar[h][k] * X[k][d]   (threads: h = tid>>6, d = tid&63)
    {
        const int h = tid >> 6, d = tid & 63;
        const float* p = pb + h * SS;
        float a2 = 0.f, a3 = 0.f;
        #pragma unroll 8
        for (int k = 0; k < 128; k += 2) {
            a2 = fmaf(p[k],     Xg[k * HH + d],       a2);
            a3 = fmaf(p[k + 1], Xg[(k + 1) * HH + d], a3);
        }
        ys[h][d] = a2 + a3;
    }
    __syncthreads();

    // obar[c] = ys[c/32] . Wv_row(128+c) + bv[c]
    if (tid < 64) {
        const int h = tid >> 5;
        float a2 = bq[f * QN + 128 + tid];
        const float4* wr = (const float4*)(Wq + ((size_t)f * QN + 128 + tid) * HH);
        #pragma unroll
        for (int d4 = 0; d4 < 16; d4++) {
            float4 wv = wr[d4];
            a2 = fmaf(ys[h][d4 * 4 + 0], wv.x, a2);
            a2 = fmaf(ys[h][d4 * 4 + 1], wv.y, a2);
            a2 = fmaf(ys[h][d4 * 4 + 2], wv.z, a2);
            a2 = fmaf(ys[h][d4 * 4 + 3], wv.w, a2);
        }
        obar[tid] = a2;
    }
    __syncthreads();

    // pooled = obar @ Wout^T + bout
    if (tid < 64) {
        float a2 = bout[f * 64 + tid];
        const float4* wr = (const float4*)(Wout + (size_t)f * 64 * 64 + tid * 64);
        #pragma unroll
        for (int h4 = 0; h4 < 16; h4++) {
            float4 wv = wr[h4];
            a2 = fmaf(obar[h4 * 4 + 0], wv.x, a2);
            a2 = fmaf(obar[h4 * 4 + 1], wv.y, a2);
            a2 = fmaf(obar[h4 * 4 + 2], wv.z, a2);
            a2 = fmaf(obar[h4 * 4 + 3], wv.w, a2);
        }
        g_comb[b][br * (FF * HH) + f * HH + tid] = a2;
    }
}

// ---------------- final: static/time MLPs + fc --------------------------------
__global__ void final_kernel(
    const float* __restrict__ stat,  // [B,32]
    const float* __restrict__ tg,    // [B,1]
    const float* __restrict__ d1w, const float* __restrict__ d1b,
    const float* __restrict__ d2w, const float* __restrict__ d2b,
    const float* __restrict__ t1w, const float* __restrict__ t1b,
    const float* __restrict__ t2w, const float* __restrict__ t2b,
    const float* __restrict__ fcw, const float* __restrict__ fcb,
    float* __restrict__ out)
{
    __shared__ float s1[64], t1s[16], tail[40], red[2][128];
    const int b = blockIdx.x, t = threadIdx.x;  // 128 threads

    if (t < 64) {
        float a = d1b[t];
        #pragma unroll
        for (int i = 0; i < 32; i++) a = fmaf(stat[b * 32 + i], d1w[t * 32 + i], a);
        s1[t] = fmaxf(a, 0.f);
    }
    if (t < 16) t1s[t] = fmaxf(fmaf(tg[b], t1w[t], t1b[t]), 0.f);
    __syncthreads();
    if (t < 32) {
        float a = d2b[t];
        #pragma unroll
        for (int i = 0; i < 64; i++) a = fmaf(s1[i], d2w[t * 64 + i], a);
        tail[t] = fmaxf(a, 0.f);
    }
    if (t >= 32 && t < 40) {
        int j = t - 32;
        float a = t2b[j];
        #pragma unroll
        for (int i = 0; i < 16; i++) a = fmaf(t1s[i], t2w[j * 16 + i], a);
        tail[t] = fmaxf(a, 0.f);
    }
    __syncthreads();

    float a0 = 0.f, a1 = 0.f;
    for (int c = t; c < 2088; c += 128) {
        float v = (c < 2048) ? g_comb[b][c] : tail[c - 2048];
        a0 = fmaf(v, fcw[c], a0);
        a1 = fmaf(v, fcw[2088 + c], a1);
    }
    red[0][t] = a0; red[1][t] = a1;
    __syncthreads();
    for (int off = 64; off >= 1; off >>= 1) {
        if (t < off) { red[0][t] += red[0][t + off]; red[1][t] += red[1][t + off]; }
        __syncthreads();
    }
    if (t == 0) {
        out[b * 2 + 0] = red[0][0] + fcb[0];
        out[b * 2 + 1] = red[1][0] + fcb[1];
    }
}

// ---------------- launch ------------------------------------------------------
extern "C" void kernel_launch(void* const* d_in, const int* in_sizes, int n_in,
                              void* d_out, int out_size)
{
    (void)in_sizes; (void)n_in; (void)out_size;
    float* out = (float*)d_out;

    cudaFuncSetAttribute(attn_kernel, cudaFuncAttributeMaxDynamicSharedMemorySize, ATTN_SMEM);

    // LSTM: both branches, batch-chunk 8 -> 256 CTAs = one full wave
    lstm_kernel<<<dim3(8, 16, 2), 256>>>(
        (const float*)d_in[0], (const float*)d_in[1],
        (const float*)d_in[4], (const float*)d_in[5],
        (const float*)d_in[6], (const float*)d_in[7],
        (const float*)d_in[8], (const float*)d_in[9],
        (const float*)d_in[10], (const float*)d_in[11]);

    // fused QK + attention: probs + colmean only
    attn_kernel<<<dim3(64, 16, 2), 512, ATTN_SMEM>>>(
        (const float*)d_in[12], (const float*)d_in[13],
        (const float*)d_in[16], (const float*)d_in[17],
        out);

    // pooled tail (V-elimination algebra), full-width threads
    post_kernel<<<dim3(64, 16, 2), 128>>>(
        (const float*)d_in[12], (const float*)d_in[13],
        (const float*)d_in[14], (const float*)d_in[15],
        (const float*)d_in[16], (const float*)d_in[17],
        (const float*)d_in[18], (const float*)d_in[19]);

    // final MLPs + fc
    final_kernel<<<64, 128>>>(
        (const float*)d_in[2], (const float*)d_in[3],
        (const float*)d_in[20], (const float*)d_in[21],
        (const float*)d_in[22], (const float*)d_in[23],
        (const float*)d_in[24], (const float*)d_in[25],
        (const float*)d_in[26], (const float*)d_in[27],
        (const float*)d_in[28], (const float*)d_in[29],
        out);
}